// round 16
// baseline (speedup 1.0000x reference)
#include <cuda_runtime.h>
#include <cuda_fp16.h>
#include <math.h>
#include <stdint.h>

#define B 128
#define S_SRC 128
#define S_TRG 64
#define H 1024
#define KE 1024
#define KDR 1344
#define KSE 320
#define KAE 576
#define ECH 16
#define DCH 21
#define NTH 512
#define STGB (160*72*2)
#define ENC_SMEM ((ECH*32*72 + 3*160*72)*2)
#define DEC_SMEM ((DCH*32*72 + 3*160*72)*2)
#define GEN_SMEM 55296

__device__ __half g_WerH[4096*KE],  g_WerL[4096*KE];
__device__ __half g_WdrH[4096*KDR], g_WdrL[4096*KDR];
__device__ __half g_WeiH[4096*KSE], g_WeiL[4096*KSE];
__device__ __half g_WdiH[4096*KAE], g_WdiL[4096*KAE];
__device__ __half g_WqkH[128*1024], g_WqkL[128*1024];
__device__ __half g_WqvH[320*1024], g_WqvL[320*1024];
__device__ __half g_WaH[128*1024],  g_WaL[128*1024];
__device__ __half g_Wh1H[2048*1024], g_Wh1L[2048*1024];
__device__ __half g_Wh2H[1024*2048], g_Wh2L[1024*2048];
__device__ __half g_Wc1H[2048*1024], g_Wc1L[2048*1024];
__device__ __half g_Wc2H[1024*2048], g_Wc2L[1024*2048];

__device__ __half g_se[(size_t)S_SRC*B*KSE];
__device__ __half g_ae[(size_t)S_TRG*B*KAE];
__device__ float g_encpre[(size_t)S_SRC*B*4096];
__device__ float g_decpre[(size_t)S_TRG*B*4096];
__device__ __half g_sh[(size_t)B*S_SRC*H];
__device__ float g_qkey[(size_t)B*S_SRC*112];
__device__ float g_qval[(size_t)B*S_SRC*304];
__device__ __half g_eh[2*B*H];
__device__ __half g_dA[2*B*KDR];
__device__ float g_ec[B*H], g_dc[B*H];
__device__ __half g_ecA[B*H];
__device__ __half g_t1[B*2048];
__device__ float g_akey[B*112];
__device__ unsigned g_bar1, g_bar2;

#define CP_COMMIT asm volatile("cp.async.commit_group;" ::: "memory")
#define CP_WAIT0  asm volatile("cp.async.wait_group 0;" ::: "memory")
#define CP_WAIT1  asm volatile("cp.async.wait_group 1;" ::: "memory")

__device__ __forceinline__ float tanh_ap(float x) {
    float r; asm("tanh.approx.f32 %0, %1;" : "=f"(r) : "f"(x)); return r;
}
__device__ __forceinline__ float sig_ap(float x) {
    return fmaf(tanh_ap(x * 0.5f), 0.5f, 0.5f);
}
__device__ __forceinline__ void ldmx4(uint32_t a, uint32_t* r) {
    asm volatile("ldmatrix.sync.aligned.m8n8.x4.shared.b16 {%0,%1,%2,%3}, [%4];"
                 : "=r"(r[0]),"=r"(r[1]),"=r"(r[2]),"=r"(r[3]) : "r"(a));
}
__device__ __forceinline__ void ldmx2(uint32_t a, uint32_t* r) {
    asm volatile("ldmatrix.sync.aligned.m8n8.x2.shared.b16 {%0,%1}, [%2];"
                 : "=r"(r[0]),"=r"(r[1]) : "r"(a));
}
__device__ __forceinline__ void mma16816(float* c, const uint32_t* a, const uint32_t* b) {
    asm volatile("mma.sync.aligned.m16n8k16.row.col.f32.f16.f16.f32 "
                 "{%0,%1,%2,%3},{%4,%5,%6,%7},{%8,%9},{%0,%1,%2,%3};"
                 : "+f"(c[0]),"+f"(c[1]),"+f"(c[2]),"+f"(c[3])
                 : "r"(a[0]),"r"(a[1]),"r"(a[2]),"r"(a[3]),"r"(b[0]),"r"(b[1]));
}
__device__ __forceinline__ void cpa16(uint32_t d, const void* s) {
    asm volatile("cp.async.cg.shared.global [%0], [%1], 16;" :: "r"(d),"l"(s));
}
__device__ __forceinline__ void grid_sync(unsigned* bar, unsigned target) {
    __syncthreads();
    if (threadIdx.x == 0) {
        __threadfence();
        atomicAdd(bar, 1u);
        volatile unsigned* vb = (volatile unsigned*)bar;
        while (*vb < target) __nanosleep(64);
        __threadfence();
    }
    __syncthreads();
}

// ---- setup kernels ----
__global__ void convw_kernel(__half* dh, __half* dl,
                             const float* __restrict__ s1, const float* __restrict__ s2,
                             int Npad, int Nreal, int Kpad, int Kreal, int lds, int mode) {
    int64_t tot = (int64_t)Npad * Kpad;
    int64_t stride = (int64_t)gridDim.x * blockDim.x;
    for (int64_t i = (int64_t)blockIdx.x*blockDim.x + threadIdx.x; i < tot; i += stride) {
        int n = (int)(i / Kpad), k = (int)(i % Kpad);
        float v = 0.f;
        if (mode == 0) { if (n < Nreal && k < Kreal) v = s1[(int64_t)n*lds + k]; }
        else {
            int orig = (n & 3)*1024 + (n >> 2);
            if (mode == 1) { if (k < Kreal) v = s1[(int64_t)orig*lds + k]; }
            else {
                if (k < 1024) v = s1[(int64_t)orig*1024 + k];
                else if (k < 1324) v = s2[(int64_t)orig*856 + 556 + (k-1024)];
            }
        }
        __half hv = __float2half(v);
        dh[i] = hv;
        if (dl) dl[i] = __float2half(v - __half2float(hv));
    }
}

__global__ void convw_enc_kernel(const float* __restrict__ Whh, const float* __restrict__ Wih) {
    const int64_t n1 = (int64_t)4096 * KE;
    const int64_t n2 = (int64_t)4096 * KSE;
    int64_t stride = (int64_t)gridDim.x * blockDim.x;
    for (int64_t i = (int64_t)blockIdx.x*blockDim.x + threadIdx.x; i < n1; i += stride) {
        {
            int n = (int)(i / KE), k = (int)(i % KE);
            int orig = (n & 3)*1024 + (n >> 2);
            float v = Whh[(int64_t)orig*1024 + k];
            __half hv = __float2half(v);
            g_WerH[i] = hv;
            g_WerL[i] = __float2half(v - __half2float(hv));
        }
        if (i < n2) {
            int n = (int)(i / KSE), k = (int)(i % KSE);
            int orig = (n & 3)*1024 + (n >> 2);
            float v = (k < 300) ? Wih[(int64_t)orig*300 + k] : 0.f;
            __half hv = __float2half(v);
            g_WeiH[i] = hv;
            g_WeiL[i] = __float2half(v - __half2float(hv));
        }
    }
}

__global__ void gather_kernel(const int* __restrict__ src_seqs, const int* __restrict__ trg_nt,
                              const int* __restrict__ par_nt, const int* __restrict__ par_lex,
                              const float* __restrict__ lex_emb, const float* __restrict__ nt_emb) {
    if (blockIdx.x == 0 && threadIdx.x == 0) { g_bar1 = 0u; g_bar2 = 0u; }
    const int64_t nse = (int64_t)S_SRC*B*KSE;
    const int64_t nae = (int64_t)S_TRG*B*KAE;
    int64_t stride = (int64_t)gridDim.x * blockDim.x;
    __half z16 = __float2half(0.f);
    for (int64_t i = (int64_t)blockIdx.x*blockDim.x + threadIdx.x; i < nse; i += stride) {
        {
            int d = (int)(i % KSE), r = (int)(i / KSE);
            int s = r >> 7, b = r & 127;
            float v = (d < 300) ? lex_emb[(int64_t)src_seqs[b*S_SRC+s]*300 + d] : 0.f;
            g_se[i] = __float2half(v);
        }
        if (i < nae) {
            int d = (int)(i % KAE), r = (int)(i / KAE);
            int t = r >> 7, b = r & 127;
            float v = 0.f;
            if (d < 128)      v = nt_emb[(int64_t)trg_nt[b*S_TRG+t]*128 + d];
            else if (d < 256) v = nt_emb[(int64_t)par_nt[b*S_TRG+t]*128 + (d-128)];
            else if (d < 556) v = lex_emb[(int64_t)par_lex[b*S_TRG+t]*300 + (d-256)];
            g_ae[i] = __float2half(v);
        }
        if (i < 2*B*KDR) g_dA[i] = z16;
        if (i < 2*B*H)   g_eh[i] = z16;
        if (i < B*H)     g_ec[i] = 0.f;
    }
}

// ============ persistent recurrence machinery (512 threads, 16 warps) ============
__device__ __forceinline__ void stream_chunk(uint32_t st, int t, int k0,
    const __half* __restrict__ A, int ldA,
    const __half* __restrict__ Wl, int ldW, int nbase)
{
    for (int u = t; u < 1280; u += NTH) {
        int row = u >> 3, grp = u & 7;
        const __half* src;
        if (row < 128) src = A + (int64_t)row*ldA + k0 + grp*8;
        else           src = Wl + (int64_t)(nbase + row - 128)*ldW + k0 + grp*8;
        cpa16(st + (uint32_t)(row*72 + grp*8)*2u, src);
    }
    CP_COMMIT;
}

template<int KCH>
__device__ __forceinline__ void load_resident(uint32_t smW, int t,
    const __half* __restrict__ Whg, int ldW, int nbase)
{
    for (int idx = t; idx < KCH*256; idx += NTH) {
        int c = idx >> 8, rr = (idx >> 3) & 31, grp = idx & 7;
        cpa16(smW + (uint32_t)((c*32 + rr)*72 + grp*8)*2u,
              Whg + (int64_t)(nbase + rr)*ldW + c*64 + grp*8);
    }
    CP_COMMIT; CP_WAIT0;
    __syncthreads();
}

// warp tile: 16 rows (wm = w&7) x 16 cols (wn = w>>3)
__device__ __forceinline__ void mma_chunk(uint32_t smWc, uint32_t st,
    int lane, int wm, int wn, float acc[2][4])
{
#pragma unroll
    for (int kk16 = 0; kk16 < 64; kk16 += 16) {
        uint32_t bh[2][2], bl[2][2];
#pragma unroll
        for (int nf = 0; nf < 2; nf++) {
            int rowW = wn*16 + nf*8 + (lane & 7);
            int kcol = kk16 + ((lane >> 3) & 1)*8;
            ldmx2(smWc + (uint32_t)(rowW*72 + kcol)*2u, bh[nf]);
            ldmx2(st + (uint32_t)((128 + rowW)*72 + kcol)*2u, bl[nf]);
        }
        int rowA = wm*16 + (lane & 7) + ((lane >> 3) & 1)*8;
        int kcol = kk16 + ((lane >> 4) & 1)*8;
        uint32_t a4[4];
        ldmx4(st + (uint32_t)(rowA*72 + kcol)*2u, a4);
#pragma unroll
        for (int nf = 0; nf < 2; nf++) {
            mma16816(acc[nf], a4, bh[nf]);
            mma16816(acc[nf], a4, bl[nf]);
        }
    }
}

template<int KCH>
__device__ __forceinline__ void gemm_phase(uint32_t smW, uint32_t smS, int t, int lane,
    int wm, int wn,
    const __half* __restrict__ A, int ldA,
    const __half* __restrict__ Wlg, int ldW, int nbase, float acc[2][4])
{
    stream_chunk(smS, t, 0, A, ldA, Wlg, ldW, nbase);
    stream_chunk(smS + STGB, t, 64, A, ldA, Wlg, ldW, nbase);
    for (int c = 0; c < KCH; c++) {
        if (c < KCH - 1) { CP_WAIT1; } else { CP_WAIT0; }
        __syncthreads();
        if (c + 2 < KCH)
            stream_chunk(smS + ((c+2)%3)*STGB, t, (c+2)*64, A, ldA, Wlg, ldW, nbase);
        mma_chunk(smW + (uint32_t)c*(32*72*2), smS + (c%3)*STGB, lane, wm, wn, acc);
    }
    __syncthreads();
}

// ---------------- persistent encoder ----------------
__global__ __launch_bounds__(NTH) void enc_persist(const float* __restrict__ biasv,
                                                   const int* __restrict__ lens) {
    extern __shared__ char smraw[];
    const uint32_t smb = (uint32_t)__cvta_generic_to_shared(smraw);
    const uint32_t smW = smb;
    const uint32_t smS = smb + (uint32_t)(ECH*32*72*2);
    const int t = threadIdx.x;
    const int lane = t & 31, w = t >> 5;
    const int wm = w & 7, wn = w >> 3;
    const int nbase = blockIdx.x*32;
    const int g2 = lane >> 2, q2 = (lane & 3)*2;
    const int b = t & 127;
    const int jj0 = (t >> 7)*2;
    const int Lb = lens[b];
    __half z16 = __float2half(0.f);

    float creg[2] = {0.f, 0.f};
    __half hreg[2] = {z16, z16};
    float bgate[2][4];
#pragma unroll
    for (int idx = 0; idx < 2; idx++) {
        int jglob = (nbase >> 2) + jj0 + idx;
        bgate[idx][0] = biasv[jglob];
        bgate[idx][1] = biasv[1024 + jglob];
        bgate[idx][2] = biasv[2048 + jglob];
        bgate[idx][3] = biasv[3072 + jglob];
    }

    load_resident<ECH>(smW, t, g_WerH, KE, nbase);

    unsigned target = 0;
    for (int s = 0; s < S_SRC; s++) {
        const int p = s & 1;
        const __half* Ah = g_eh + p*B*H;
        __half* Ho = g_eh + (p^1)*B*H;
        const float* add = g_encpre + (int64_t)s*B*4096;

        float acc[2][4];
#pragma unroll
        for (int a = 0; a < 2; a++)
#pragma unroll
            for (int r = 0; r < 4; r++) acc[a][r] = 0.f;

        gemm_phase<ECH>(smW, smS, t, lane, wm, wn, Ah, H, g_WerL, KE, nbase, acc);

        float* zb = (float*)(smraw + ECH*32*72*2);
#pragma unroll
        for (int nf = 0; nf < 2; nf++)
#pragma unroll
            for (int r = 0; r < 4; r++) {
                int row = wm*16 + g2 + (r >> 1)*8;
                int col = wn*16 + nf*8 + q2 + (r & 1);
                zb[row*33 + col] = acc[nf][r];
            }
        __syncthreads();

        const bool valid = s < Lb;
#pragma unroll
        for (int idx = 0; idx < 2; idx++) {
            int jj = jj0 + idx;
            int jglob = (nbase >> 2) + jj;
            float4 pre = *(const float4*)&add[(int64_t)b*4096 + nbase + jj*4];
            float zi = zb[b*33 + jj*4 + 0] + pre.x + bgate[idx][0];
            float zf = zb[b*33 + jj*4 + 1] + pre.y + bgate[idx][1];
            float zg = zb[b*33 + jj*4 + 2] + pre.z + bgate[idx][2];
            float zo = zb[b*33 + jj*4 + 3] + pre.w + bgate[idx][3];
            float c2 = sig_ap(zf)*creg[idx] + sig_ap(zi)*tanh_ap(zg);
            float h2 = sig_ap(zo)*tanh_ap(c2);
            if (valid) { creg[idx] = c2; hreg[idx] = __float2half(h2); }
            Ho[b*H + jglob] = hreg[idx];
            g_sh[((int64_t)b*S_SRC + s)*H + jglob] = valid ? hreg[idx] : z16;
        }
        grid_sync(&g_bar1, target += 128);
    }
#pragma unroll
    for (int idx = 0; idx < 2; idx++)
        g_ec[b*H + (nbase >> 2) + jj0 + idx] = creg[idx];
}

// ---------------- persistent decoder ----------------
__device__ __forceinline__ void stream_mini(uint32_t st, int t, int k0,
    const __half* __restrict__ A, int nb8)
{
    for (int u = t; u < 1152; u += NTH) {
        int row = u >> 3, grp = u & 7;
        const __half* src;
        if (row < 128)      src = A + (int64_t)row*KDR + k0 + grp*8;
        else if (row < 136) src = g_WaH + (int64_t)(nb8 + row - 128)*1024 + k0 + grp*8;
        else                src = g_WaL + (int64_t)(nb8 + row - 136)*1024 + k0 + grp*8;
        cpa16(st + (uint32_t)(row*72 + grp*8)*2u, src);
    }
    CP_COMMIT;
}

__global__ __launch_bounds__(NTH) void dec_persist(const float* __restrict__ biasv,
                                                   const float* __restrict__ ba_,
                                                   const int* __restrict__ lens,
                                                   float* __restrict__ outF) {
    extern __shared__ char smraw[];
    __shared__ float s_ak[112];
    __shared__ float s_en[128];
    __shared__ float s_red[8];
    const uint32_t smb = (uint32_t)__cvta_generic_to_shared(smraw);
    const uint32_t smW = smb;
    const uint32_t smS = smb + (uint32_t)(DCH*32*72*2);
    const int t = threadIdx.x;
    const int lane = t & 31, w = t >> 5;
    const int wm = w & 7, wn = w >> 3;
    const int nbase = blockIdx.x*32;
    const int g2 = lane >> 2, q2 = (lane & 3)*2;
    const int myb = blockIdx.x;
    const int b = t & 127;
    const int jj0 = (t >> 7)*2;

    float creg[2];
    float bgate[2][4];
#pragma unroll
    for (int idx = 0; idx < 2; idx++) {
        int jglob = (nbase >> 2) + jj0 + idx;
        creg[idx] = g_dc[b*H + jglob];
        bgate[idx][0] = biasv[jglob];
        bgate[idx][1] = biasv[1024 + jglob];
        bgate[idx][2] = biasv[2048 + jglob];
        bgate[idx][3] = biasv[3072 + jglob];
    }

    load_resident<DCH>(smW, t, g_WdrH, KDR, nbase);

    unsigned target = 0;
    for (int ts = 0; ts < S_TRG; ts++) {
        const int p = ts & 1;
        __half* dAp = g_dA + p*B*KDR;
        __half* nAp = g_dA + (p^1)*B*KDR;

        // A1: a_key mini-GEMM (blocks 0..13; math on warps 0..7, all stage)
        if (blockIdx.x < 14) {
            const int nb8 = blockIdx.x*8;
            float acm[4] = {0.f,0.f,0.f,0.f};
            stream_mini(smS, t, 0, dAp, nb8);
            for (int c = 0; c < 16; c++) {
                if (c < 15) stream_mini(smS + ((c+1)&1)*STGB, t, (c+1)*64, dAp, nb8);
                if (c < 15) { CP_WAIT1; } else { CP_WAIT0; }
                __syncthreads();
                if (w < 8) {
                    uint32_t st = smS + (c & 1)*STGB;
#pragma unroll
                    for (int kk16 = 0; kk16 < 64; kk16 += 16) {
                        uint32_t bh[2], bl[2];
                        int rowW = lane & 7;
                        int kcolW = kk16 + ((lane >> 3) & 1)*8;
                        ldmx2(st + (uint32_t)((128 + rowW)*72 + kcolW)*2u, bh);
                        ldmx2(st + (uint32_t)((136 + rowW)*72 + kcolW)*2u, bl);
                        int rowA = w*16 + (lane & 7) + ((lane >> 3) & 1)*8;
                        int kcolA = kk16 + ((lane >> 4) & 1)*8;
                        uint32_t a4[4];
                        ldmx4(st + (uint32_t)(rowA*72 + kcolA)*2u, a4);
                        mma16816(acm, a4, bh);
                        mma16816(acm, a4, bl);
                    }
                }
                __syncthreads();
            }
            if (w < 8) {
#pragma unroll
                for (int r = 0; r < 4; r++) {
                    int row = w*16 + g2 + (r >> 1)*8;
                    int gc = nb8 + q2 + (r & 1);
                    float bb = (gc < 100) ? ba_[gc] : 0.f;
                    g_akey[row*112 + gc] = tanh_ap(acm[r] + bb);
                }
            }
        }
        grid_sync(&g_bar2, target += 128);

        // A2: softmax + context for batch myb
        {
            if (t < 112) s_ak[t] = g_akey[myb*112 + t];
            __syncthreads();
            float ex = 0.f;
            if (t < 128) {
                int L = lens[myb];
                const float* qk = g_qkey + ((int64_t)myb*S_SRC + t)*112;
                float pp = 0.f;
#pragma unroll 4
                for (int d = 0; d < 100; d++) pp = fmaf(qk[d], s_ak[d], pp);
                float e = (t < L) ? pp : -1e9f;
                float mx = e;
                for (int o = 16; o; o >>= 1) mx = fmaxf(mx, __shfl_xor_sync(0xffffffffu, mx, o));
                if (lane == 0) s_red[w] = mx;
                s_en[t] = e;
            }
            __syncthreads();
            if (t < 128) {
                float mx = fmaxf(fmaxf(s_red[0], s_red[1]), fmaxf(s_red[2], s_red[3]));
                ex = expf(s_en[t] - mx);
                float sm = ex;
                for (int o = 16; o; o >>= 1) sm += __shfl_xor_sync(0xffffffffu, sm, o);
                if (lane == 0) s_red[4 + w] = sm;
            }
            __syncthreads();
            if (t < 128) s_en[t] = ex;
            __syncthreads();
            float denom = s_red[4] + s_red[5] + s_red[6] + s_red[7];
            for (int d = t; d < 300; d += NTH) {
                float c = 0.f;
#pragma unroll 4
                for (int s2 = 0; s2 < S_SRC; s2++)
                    c = fmaf(s_en[s2], g_qval[((int64_t)myb*S_SRC + s2)*304 + d], c);
                c /= denom;
                dAp[(int64_t)myb*KDR + 1024 + d] = __float2half(c);
            }
        }
        grid_sync(&g_bar2, target += 128);

        // B: recurrent GEMM + LSTM epilogue
        {
            const float* add = g_decpre + (int64_t)ts*B*4096;
            float acc[2][4];
#pragma unroll
            for (int a = 0; a < 2; a++)
#pragma unroll
                for (int r = 0; r < 4; r++) acc[a][r] = 0.f;

            gemm_phase<DCH>(smW, smS, t, lane, wm, wn, dAp, KDR, g_WdrL, KDR, nbase, acc);

            float* zb = (float*)(smraw + DCH*32*72*2);
#pragma unroll
            for (int nf = 0; nf < 2; nf++)
#pragma unroll
                for (int r = 0; r < 4; r++) {
                    int row = wm*16 + g2 + (r >> 1)*8;
                    int col = wn*16 + nf*8 + q2 + (r & 1);
                    zb[row*33 + col] = acc[nf][r];
                }
            __syncthreads();

#pragma unroll
            for (int idx = 0; idx < 2; idx++) {
                int jj = jj0 + idx;
                int jglob = (nbase >> 2) + jj;
                float4 pre = *(const float4*)&add[(int64_t)b*4096 + nbase + jj*4];
                float zi = zb[b*33 + jj*4 + 0] + pre.x + bgate[idx][0];
                float zf = zb[b*33 + jj*4 + 1] + pre.y + bgate[idx][1];
                float zg = zb[b*33 + jj*4 + 2] + pre.z + bgate[idx][2];
                float zo = zb[b*33 + jj*4 + 3] + pre.w + bgate[idx][3];
                float c2 = sig_ap(zf)*creg[idx] + sig_ap(zi)*tanh_ap(zg);
                float h2 = sig_ap(zo)*tanh_ap(c2);
                creg[idx] = c2;
                nAp[(int64_t)b*KDR + jglob] = __float2half(h2);
                outF[((int64_t)b*S_TRG + ts)*H + jglob] = h2;
            }
        }
        grid_sync(&g_bar2, target += 128);
    }
}

// ---------------- one-shot GEMM (R14, 256 threads, pipelined) ----------------
__device__ __forceinline__ void load_chunk_g(uint32_t smb, int buf, int t, int k0,
    const __half* __restrict__ A, int ldA, int mbase,
    const __half* __restrict__ Wh, const __half* __restrict__ Wl, int ldW, int nbase)
{
#pragma unroll
    for (int i = 0; i < 4; i++) {
        int u = i*256 + t;
        int row = u >> 3, grp = u & 7;
        const __half* src = A + (int64_t)(mbase + row)*ldA + k0 + grp*8;
        cpa16(smb + (uint32_t)buf*18432u + (uint32_t)(row*72 + grp*8)*2u, src);
    }
#pragma unroll
    for (int i = 0; i < 2; i++) {
        int u = i*256 + t;
        int hl = u >> 8, rem = u & 255;
        int row = rem >> 3, grp = rem & 7;
        const __half* src = (hl ? Wl : Wh) + (int64_t)(nbase + row)*ldW + k0 + grp*8;
        cpa16(smb + 36864u + (uint32_t)(((buf*2 + hl)*32 + row)*72 + grp*8)*2u, src);
    }
    CP_COMMIT;
}

__device__ __forceinline__ void ldB2g(uint32_t wbh, uint32_t wbl, int lane, int wn, int kk16,
                                      uint32_t bh[2][2], uint32_t bl[2][2]) {
#pragma unroll
    for (int nf = 0; nf < 2; nf++) {
        int rowW = wn*16 + nf*8 + (lane & 7);
        int kcol = kk16 + ((lane >> 3) & 1)*8;
        ldmx2(wbh + (uint32_t)(rowW*72 + kcol)*2u, bh[nf]);
        ldmx2(wbl + (uint32_t)(rowW*72 + kcol)*2u, bl[nf]);
    }
}
__device__ __forceinline__ void ldA2g(uint32_t ab, int lane, int wm, int kk16, uint32_t a4[2][4]) {
#pragma unroll
    for (int mf = 0; mf < 2; mf++) {
        int rowA = wm*32 + mf*16 + (lane & 7) + ((lane >> 3) & 1)*8;
        int kcol = kk16 + ((lane >> 4) & 1)*8;
        ldmx4(ab + (uint32_t)(rowA*72 + kcol)*2u, a4[mf]);
    }
}

template<int OUT, int ACT>
__global__ __launch_bounds__(256) void mma_gemm(
    const __half* __restrict__ A, int ldA,
    const __half* __restrict__ Wh, const __half* __restrict__ Wl, int ldW,
    int N, int KT, const float* __restrict__ bias,
    float* __restrict__ Cf, __half* __restrict__ Ch, int ldC)
{
    extern __shared__ char smraw[];
    uint32_t smb = (uint32_t)__cvta_generic_to_shared(smraw);
    const int t = threadIdx.x;
    const int lane = t & 31, w = t >> 5;
    const int wm = w & 3, wn = w >> 2;
    const int mbase = blockIdx.y*128;
    const int nbase = blockIdx.x*32;

    float acc[2][2][4];
#pragma unroll
    for (int a = 0; a < 2; a++)
#pragma unroll
        for (int b2 = 0; b2 < 2; b2++)
#pragma unroll
            for (int r = 0; r < 4; r++) acc[a][b2][r] = 0.f;

    load_chunk_g(smb, 0, t, 0, A, ldA, mbase, Wh, Wl, ldW, nbase);

    for (int kc = 0; kc < KT; kc++) {
        const int cur = kc & 1;
        if (kc + 1 < KT) {
            load_chunk_g(smb, cur ^ 1, t, (kc+1)*64, A, ldA, mbase, Wh, Wl, ldW, nbase);
            CP_WAIT1;
        } else { CP_WAIT0; }
        __syncthreads();

        const uint32_t ab  = smb + (uint32_t)cur*18432u;
        const uint32_t wbh = smb + 36864u + (uint32_t)((cur*2+0)*32*72)*2u;
        const uint32_t wbl = smb + 36864u + (uint32_t)((cur*2+1)*32*72)*2u;
        uint32_t bh[2][2][2], bl[2][2][2], a4[2][2][4];
        ldB2g(wbh, wbl, lane, wn, 0, bh[0], bl[0]);
        ldA2g(ab, lane, wm, 0, a4[0]);
#pragma unroll
        for (int k = 0; k < 4; k++) {
            const int c2 = k & 1, nx = c2 ^ 1;
            if (k < 3) {
                ldB2g(wbh, wbl, lane, wn, (k+1)*16, bh[nx], bl[nx]);
                ldA2g(ab, lane, wm, (k+1)*16, a4[nx]);
            }
#pragma unroll
            for (int mf = 0; mf < 2; mf++)
#pragma unroll
                for (int nf = 0; nf < 2; nf++) {
                    mma16816(acc[mf][nf], a4[c2][mf], bh[c2][nf]);
                    mma16816(acc[mf][nf], a4[c2][mf], bl[c2][nf]);
                }
        }
        __syncthreads();
    }

    const int g2 = lane >> 2, q2 = (lane & 3)*2;
#pragma unroll
    for (int mf = 0; mf < 2; mf++)
#pragma unroll
        for (int nf = 0; nf < 2; nf++)
#pragma unroll
            for (int r = 0; r < 4; r++) {
                int row = mbase + wm*32 + mf*16 + g2 + (r >> 1)*8;
                int col = nbase + wn*16 + nf*8 + q2 + (r & 1);
                if (col < N) {
                    float v = acc[mf][nf][r];
                    if (bias) v += bias[col];
                    if (ACT == 1) v = fmaxf(v, 0.f);
                    if (ACT == 2) v = tanhf(v);
                    if (OUT == 0) Cf[(int64_t)row*ldC + col] = v;
                    else Ch[(int64_t)row*ldC + col] = __float2half(v);
                }
            }
}

// ---------------- launcher ----------------
#define GSA(p, s) cudaGetSymbolAddress((void**)&p, s)

extern "C" void kernel_launch(void* const* d_in, const int* in_sizes, int n_in,
                              void* d_out, int out_size) {
    const int* src_seqs = (const int*)d_in[0];
    const int* src_len = (const int*)d_in[1];
    const int* trg_nt = (const int*)d_in[2];
    const int* par_nt = (const int*)d_in[3];
    const int* par_lex = (const int*)d_in[4];
    const float* lex_emb = (const float*)d_in[5];
    const float* nt_emb = (const float*)d_in[6];
    const float* enc_Wih = (const float*)d_in[7];
    const float* enc_Whh = (const float*)d_in[8];
    const float* enc_b = (const float*)d_in[9];
    const float* dec_Wih = (const float*)d_in[10];
    const float* dec_Whh = (const float*)d_in[11];
    const float* dec_b = (const float*)d_in[12];
    const float* Wh1 = (const float*)d_in[13];
    const float* bh1 = (const float*)d_in[14];
    const float* Wh2 = (const float*)d_in[15];
    const float* bh2 = (const float*)d_in[16];
    const float* Wc1 = (const float*)d_in[17];
    const float* bc1 = (const float*)d_in[18];
    const float* Wc2 = (const float*)d_in[19];
    const float* bc2 = (const float*)d_in[20];
    const float* Wa = (const float*)d_in[21];
    const float* ba = (const float*)d_in[22];
    const float* Wqk = (const float*)d_in[23];
    const float* bqk = (const float*)d_in[24];
    const float* Wqv = (const float*)d_in[25];
    const float* bqv = (const float*)d_in[26];
    float* out = (float*)d_out;

    cudaFuncSetAttribute(mma_gemm<0,0>, cudaFuncAttributeMaxDynamicSharedMemorySize, GEN_SMEM);
    cudaFuncSetAttribute(mma_gemm<0,2>, cudaFuncAttributeMaxDynamicSharedMemorySize, GEN_SMEM);
    cudaFuncSetAttribute(mma_gemm<1,0>, cudaFuncAttributeMaxDynamicSharedMemorySize, GEN_SMEM);
    cudaFuncSetAttribute(mma_gemm<1,1>, cudaFuncAttributeMaxDynamicSharedMemorySize, GEN_SMEM);
    cudaFuncSetAttribute(enc_persist, cudaFuncAttributeMaxDynamicSharedMemorySize, ENC_SMEM);
    cudaFuncSetAttribute(dec_persist, cudaFuncAttributeMaxDynamicSharedMemorySize, DEC_SMEM);

    __half *WerH,*WerL,*WdrH,*WdrL,*WaH,*WaL;
    __half *WeiH,*WeiL,*WdiH,*WdiL,*WqkH,*WqkL,*WqvH,*WqvL;
    __half *Wh1H,*Wh1L,*Wh2H,*Wh2L,*Wc1H,*Wc1L,*Wc2H,*Wc2L;
    __half *se,*ae,*sh,*eh,*dA,*ecA,*t1;
    float *encpre,*decpre,*qkey,*qval,*ec,*dc;
    GSA(WerH,g_WerH); GSA(WerL,g_WerL); GSA(WdrH,g_WdrH); GSA(WdrL,g_WdrL);
    GSA(WaH,g_WaH);   GSA(WaL,g_WaL);
    GSA(WeiH,g_WeiH); GSA(WeiL,g_WeiL); GSA(WdiH,g_WdiH); GSA(WdiL,g_WdiL);
    GSA(WqkH,g_WqkH); GSA(WqkL,g_WqkL); GSA(WqvH,g_WqvH); GSA(WqvL,g_WqvL);
    GSA(Wh1H,g_Wh1H); GSA(Wh1L,g_Wh1L); GSA(Wh2H,g_Wh2H); GSA(Wh2L,g_Wh2L);
    GSA(Wc1H,g_Wc1H); GSA(Wc1L,g_Wc1L); GSA(Wc2H,g_Wc2H); GSA(Wc2L,g_Wc2L);
    GSA(se,g_se); GSA(ae,g_ae); GSA(sh,g_sh); GSA(eh,g_eh); GSA(dA,g_dA);
    GSA(ecA,g_ecA); GSA(t1,g_t1);
    GSA(encpre,g_encpre); GSA(decpre,g_decpre);
    GSA(qkey,g_qkey); GSA(qval,g_qval); GSA(ec,g_ec); GSA(dc,g_dc);

    convw_enc_kernel<<<1024, 256>>>(enc_Whh, enc_Wih);
    gather_kernel<<<2048, 256>>>(src_seqs, trg_nt, par_nt, par_lex, lex_emb, nt_emb);
    mma_gemm<0,0><<<dim3(128,128), 256, GEN_SMEM>>>(se, KSE, WeiH, WeiL, KSE,
        4096, KSE/64, nullptr, encpre, nullptr, 4096);

    // L3: encoder persistent (ncu capture target)
    enc_persist<<<128, NTH, ENC_SMEM>>>(enc_b, src_len);

    convw_kernel<<<1024, 256>>>(WdrH, WdrL, dec_Whh, dec_Wih, 4096, 0, KDR, 1324, 0, 2);
    convw_kernel<<<1024, 256>>>(WdiH, WdiL, dec_Wih, nullptr, 4096, 0, KAE, 556, 856, 1);
    convw_kernel<<<256, 256>>>(WqkH, WqkL, Wqk, nullptr, 128, 100, 1024, 1024, 1024, 0);
    convw_kernel<<<256, 256>>>(WqvH, WqvL, Wqv, nullptr, 320, 300, 1024, 1024, 1024, 0);
    convw_kernel<<<256, 256>>>(WaH,  WaL,  Wa,  nullptr, 128, 100, 1024, 1024, 1024, 0);
    convw_kernel<<<1024, 256>>>(Wh1H, Wh1L, Wh1, nullptr, 2048, 2048, 1024, 1024, 1024, 0);
    convw_kernel<<<1024, 256>>>(Wh2H, Wh2L, Wh2, nullptr, 1024, 1024, 2048, 2048, 2048, 0);
    convw_kernel<<<1024, 256>>>(Wc1H, Wc1L, Wc1, nullptr, 2048, 2048, 1024, 1024, 1024, 0);
    convw_kernel<<<1024, 256>>>(Wc2H, Wc2L, Wc2, nullptr, 1024, 1024, 2048, 2048, 2048, 0);

    mma_gemm<0,0><<<dim3(128,64), 256, GEN_SMEM>>>(ae, KAE, WdiH, WdiL, KAE,
        4096, KAE/64, nullptr, decpre, nullptr, 4096);

    mma_gemm<0,2><<<dim3(4,128), 256, GEN_SMEM>>>(sh, H, WqkH, WqkL, 1024,
        100, 16, bqk, qkey, nullptr, 112);
    mma_gemm<0,0><<<dim3(10,128), 256, GEN_SMEM>>>(sh, H, WqvH, WqvL, 1024,
        300, 16, bqv, qval, nullptr, 304);

    convw_kernel<<<256, 256>>>(ecA, nullptr, ec, nullptr, 128, 128, 1024, 1024, 1024, 0);
    mma_gemm<1,1><<<dim3(64,1), 256, GEN_SMEM>>>(eh, H, Wh1H, Wh1L, 1024,
        2048, 16, bh1, nullptr, t1, 2048);
    mma_gemm<1,0><<<dim3(32,1), 256, GEN_SMEM>>>(t1, 2048, Wh2H, Wh2L, 2048,
        1024, 32, bh2, nullptr, dA, KDR);
    mma_gemm<1,1><<<dim3(64,1), 256, GEN_SMEM>>>(ecA, H, Wc1H, Wc1L, 1024,
        2048, 16, bc1, nullptr, t1, 2048);
    mma_gemm<0,0><<<dim3(32,1), 256, GEN_SMEM>>>(t1, 2048, Wc2H, Wc2L, 2048,
        1024, 32, bc2, dc, nullptr, 1024);

    dec_persist<<<128, NTH, DEC_SMEM>>>(dec_b, ba, src_len, out);
}

// round 17
// speedup vs baseline: 1.1898x; 1.1898x over previous
#include <cuda_runtime.h>
#include <cuda_fp16.h>
#include <math.h>
#include <stdint.h>

#define B 128
#define S_SRC 128
#define S_TRG 64
#define H 1024
#define KE 1024
#define KDR 1344
#define KSE 320
#define KAE 576
#define ECH 16
#define DCH 21
#define STGB (160*72*2)
#define ENC_SMEM ((ECH*32*72 + 3*160*72)*2)
#define DEC_SMEM ((DCH*32*72 + 3*160*72)*2)
#define GEN_SMEM 55296

__device__ __half g_WerH[4096*KE],  g_WerL[4096*KE];
__device__ __half g_WdrH[4096*KDR], g_WdrL[4096*KDR];
__device__ __half g_WeiH[4096*KSE], g_WeiL[4096*KSE];
__device__ __half g_WdiH[4096*KAE], g_WdiL[4096*KAE];
__device__ __half g_WqkH[128*1024], g_WqkL[128*1024];
__device__ __half g_WqvH[320*1024], g_WqvL[320*1024];
__device__ __half g_WaH[128*1024],  g_WaL[128*1024];
__device__ __half g_Wh1H[2048*1024], g_Wh1L[2048*1024];
__device__ __half g_Wh2H[1024*2048], g_Wh2L[1024*2048];
__device__ __half g_Wc1H[2048*1024], g_Wc1L[2048*1024];
__device__ __half g_Wc2H[1024*2048], g_Wc2L[1024*2048];

__device__ __half g_se[(size_t)S_SRC*B*KSE];
__device__ __half g_ae[(size_t)S_TRG*B*KAE];
__device__ float g_encpre[(size_t)S_SRC*B*4096];
__device__ float g_decpre[(size_t)S_TRG*B*4096];
__device__ __half g_sh[(size_t)B*S_SRC*H];
__device__ float g_qkey[(size_t)B*S_SRC*112];
__device__ float g_qval[(size_t)B*S_SRC*304];
__device__ __half g_eh[2*B*H];
__device__ __half g_dA[2*B*KDR];
__device__ float g_ec[B*H], g_dc[B*H];
__device__ __half g_ecA[B*H];
__device__ __half g_t1[B*2048];
__device__ float g_akey[B*112];
__device__ unsigned g_bar1, g_bar2;

#define CP_COMMIT asm volatile("cp.async.commit_group;" ::: "memory")
#define CP_WAIT0  asm volatile("cp.async.wait_group 0;" ::: "memory")
#define CP_WAIT1  asm volatile("cp.async.wait_group 1;" ::: "memory")

__device__ __forceinline__ float tanh_ap(float x) {
    float r; asm("tanh.approx.f32 %0, %1;" : "=f"(r) : "f"(x)); return r;
}
__device__ __forceinline__ float sig_ap(float x) {
    return fmaf(tanh_ap(x * 0.5f), 0.5f, 0.5f);
}
__device__ __forceinline__ void ldmx4(uint32_t a, uint32_t* r) {
    asm volatile("ldmatrix.sync.aligned.m8n8.x4.shared.b16 {%0,%1,%2,%3}, [%4];"
                 : "=r"(r[0]),"=r"(r[1]),"=r"(r[2]),"=r"(r[3]) : "r"(a));
}
__device__ __forceinline__ void ldmx2(uint32_t a, uint32_t* r) {
    asm volatile("ldmatrix.sync.aligned.m8n8.x2.shared.b16 {%0,%1}, [%2];"
                 : "=r"(r[0]),"=r"(r[1]) : "r"(a));
}
__device__ __forceinline__ void mma16816(float* c, const uint32_t* a, const uint32_t* b) {
    asm volatile("mma.sync.aligned.m16n8k16.row.col.f32.f16.f16.f32 "
                 "{%0,%1,%2,%3},{%4,%5,%6,%7},{%8,%9},{%0,%1,%2,%3};"
                 : "+f"(c[0]),"+f"(c[1]),"+f"(c[2]),"+f"(c[3])
                 : "r"(a[0]),"r"(a[1]),"r"(a[2]),"r"(a[3]),"r"(b[0]),"r"(b[1]));
}
__device__ __forceinline__ void cpa16(uint32_t d, const void* s) {
    asm volatile("cp.async.cg.shared.global [%0], [%1], 16;" :: "r"(d),"l"(s));
}
__device__ __forceinline__ void grid_sync(unsigned* bar, unsigned target) {
    __syncthreads();
    if (threadIdx.x == 0) {
        __threadfence();
        atomicAdd(bar, 1u);
        volatile unsigned* vb = (volatile unsigned*)bar;
        while (*vb < target) __nanosleep(64);
        __threadfence();
    }
    __syncthreads();
}

// ---- setup kernels ----
__global__ void convw_kernel(__half* dh, __half* dl,
                             const float* __restrict__ s1, const float* __restrict__ s2,
                             int Npad, int Nreal, int Kpad, int Kreal, int lds, int mode) {
    int64_t tot = (int64_t)Npad * Kpad;
    int64_t stride = (int64_t)gridDim.x * blockDim.x;
    for (int64_t i = (int64_t)blockIdx.x*blockDim.x + threadIdx.x; i < tot; i += stride) {
        int n = (int)(i / Kpad), k = (int)(i % Kpad);
        float v = 0.f;
        if (mode == 0) { if (n < Nreal && k < Kreal) v = s1[(int64_t)n*lds + k]; }
        else {
            int orig = (n & 3)*1024 + (n >> 2);
            if (mode == 1) { if (k < Kreal) v = s1[(int64_t)orig*lds + k]; }
            else {
                if (k < 1024) v = s1[(int64_t)orig*1024 + k];
                else if (k < 1324) v = s2[(int64_t)orig*856 + 556 + (k-1024)];
            }
        }
        __half hv = __float2half(v);
        dh[i] = hv;
        if (dl) dl[i] = __float2half(v - __half2float(hv));
    }
}

__global__ void convw_enc_kernel(const float* __restrict__ Whh, const float* __restrict__ Wih) {
    const int64_t n1 = (int64_t)4096 * KE;
    const int64_t n2 = (int64_t)4096 * KSE;
    int64_t stride = (int64_t)gridDim.x * blockDim.x;
    for (int64_t i = (int64_t)blockIdx.x*blockDim.x + threadIdx.x; i < n1; i += stride) {
        {
            int n = (int)(i / KE), k = (int)(i % KE);
            int orig = (n & 3)*1024 + (n >> 2);
            float v = Whh[(int64_t)orig*1024 + k];
            __half hv = __float2half(v);
            g_WerH[i] = hv;
            g_WerL[i] = __float2half(v - __half2float(hv));
        }
        if (i < n2) {
            int n = (int)(i / KSE), k = (int)(i % KSE);
            int orig = (n & 3)*1024 + (n >> 2);
            float v = (k < 300) ? Wih[(int64_t)orig*300 + k] : 0.f;
            __half hv = __float2half(v);
            g_WeiH[i] = hv;
            g_WeiL[i] = __float2half(v - __half2float(hv));
        }
    }
}

__global__ void gather_kernel(const int* __restrict__ src_seqs, const int* __restrict__ trg_nt,
                              const int* __restrict__ par_nt, const int* __restrict__ par_lex,
                              const float* __restrict__ lex_emb, const float* __restrict__ nt_emb) {
    if (blockIdx.x == 0 && threadIdx.x == 0) { g_bar1 = 0u; g_bar2 = 0u; }
    const int64_t nse = (int64_t)S_SRC*B*KSE;
    const int64_t nae = (int64_t)S_TRG*B*KAE;
    int64_t stride = (int64_t)gridDim.x * blockDim.x;
    __half z16 = __float2half(0.f);
    for (int64_t i = (int64_t)blockIdx.x*blockDim.x + threadIdx.x; i < nse; i += stride) {
        {
            int d = (int)(i % KSE), r = (int)(i / KSE);
            int s = r >> 7, b = r & 127;
            float v = (d < 300) ? lex_emb[(int64_t)src_seqs[b*S_SRC+s]*300 + d] : 0.f;
            g_se[i] = __float2half(v);
        }
        if (i < nae) {
            int d = (int)(i % KAE), r = (int)(i / KAE);
            int t = r >> 7, b = r & 127;
            float v = 0.f;
            if (d < 128)      v = nt_emb[(int64_t)trg_nt[b*S_TRG+t]*128 + d];
            else if (d < 256) v = nt_emb[(int64_t)par_nt[b*S_TRG+t]*128 + (d-128)];
            else if (d < 556) v = lex_emb[(int64_t)par_lex[b*S_TRG+t]*300 + (d-256)];
            g_ae[i] = __float2half(v);
        }
        if (i < 2*B*KDR) g_dA[i] = z16;
        if (i < 2*B*H)   g_eh[i] = z16;
        if (i < B*H)     g_ec[i] = 0.f;
    }
}

// ============ persistent recurrence machinery (256 threads, R14 tiling) ============
__device__ __forceinline__ void stream_chunk(uint32_t st, int t, int k0,
    const __half* __restrict__ A, int ldA,
    const __half* __restrict__ Wl, int ldW, int nbase)
{
#pragma unroll
    for (int i = 0; i < 5; i++) {
        int u = i*256 + t;
        int row = u >> 3, grp = u & 7;
        const __half* src;
        if (row < 128) src = A + (int64_t)row*ldA + k0 + grp*8;
        else           src = Wl + (int64_t)(nbase + row - 128)*ldW + k0 + grp*8;
        cpa16(st + (uint32_t)(row*72 + grp*8)*2u, src);
    }
    CP_COMMIT;
}

template<int KCH>
__device__ __forceinline__ void load_resident(uint32_t smW, int t,
    const __half* __restrict__ Whg, int ldW, int nbase)
{
    int rr = (t >> 3) & 31, grp = t & 7;
#pragma unroll
    for (int i = 0; i < KCH; i++)
        cpa16(smW + (uint32_t)((i*32 + rr)*72 + grp*8)*2u,
              Whg + (int64_t)(nbase + rr)*ldW + i*64 + grp*8);
    CP_COMMIT; CP_WAIT0;
    __syncthreads();
}

__device__ __forceinline__ void ldB2(uint32_t smWc, uint32_t st, int lane, int wn, int kk16,
                                     uint32_t bh[2][2], uint32_t bl[2][2]) {
#pragma unroll
    for (int nf = 0; nf < 2; nf++) {
        int rowW = wn*16 + nf*8 + (lane & 7);
        int kcol = kk16 + ((lane >> 3) & 1)*8;
        ldmx2(smWc + (uint32_t)(rowW*72 + kcol)*2u, bh[nf]);
        ldmx2(st + (uint32_t)((128 + rowW)*72 + kcol)*2u, bl[nf]);
    }
}
__device__ __forceinline__ void ldA2(uint32_t st, int lane, int wm, int kk16, uint32_t a4[2][4]) {
#pragma unroll
    for (int mf = 0; mf < 2; mf++) {
        int rowA = wm*32 + mf*16 + (lane & 7) + ((lane >> 3) & 1)*8;
        int kcol = kk16 + ((lane >> 4) & 1)*8;
        ldmx4(st + (uint32_t)(rowA*72 + kcol)*2u, a4[mf]);
    }
}

__device__ __forceinline__ void mma_chunk(uint32_t smWc, uint32_t st,
    int lane, int wm, int wn, float acc[2][2][4])
{
    uint32_t bh[2][2][2], bl[2][2][2], a4[2][2][4];
    ldB2(smWc, st, lane, wn, 0, bh[0], bl[0]);
    ldA2(st, lane, wm, 0, a4[0]);
#pragma unroll
    for (int k = 0; k < 4; k++) {
        const int cur = k & 1, nxt = cur ^ 1;
        if (k < 3) {
            ldB2(smWc, st, lane, wn, (k+1)*16, bh[nxt], bl[nxt]);
            ldA2(st, lane, wm, (k+1)*16, a4[nxt]);
        }
#pragma unroll
        for (int mf = 0; mf < 2; mf++)
#pragma unroll
            for (int nf = 0; nf < 2; nf++) {
                mma16816(acc[mf][nf], a4[cur][mf], bh[cur][nf]);
                mma16816(acc[mf][nf], a4[cur][mf], bl[cur][nf]);
            }
    }
}

template<int KCH>
__device__ __forceinline__ void gemm_phase(uint32_t smW, uint32_t smS, int t, int lane,
    int wm, int wn,
    const __half* __restrict__ A, int ldA,
    const __half* __restrict__ Wlg, int ldW, int nbase, float acc[2][2][4])
{
    stream_chunk(smS, t, 0, A, ldA, Wlg, ldW, nbase);
    stream_chunk(smS + STGB, t, 64, A, ldA, Wlg, ldW, nbase);
    for (int c = 0; c < KCH; c++) {
        if (c < KCH - 1) { CP_WAIT1; } else { CP_WAIT0; }
        __syncthreads();
        if (c + 2 < KCH)
            stream_chunk(smS + ((c+2)%3)*STGB, t, (c+2)*64, A, ldA, Wlg, ldW, nbase);
        mma_chunk(smW + (uint32_t)c*(32*72*2), smS + (c%3)*STGB, lane, wm, wn, acc);
    }
    __syncthreads();
}

// ---------------- persistent encoder ----------------
__global__ __launch_bounds__(256) void enc_persist(const float* __restrict__ biasv,
                                                   const int* __restrict__ lens) {
    extern __shared__ char smraw[];
    const uint32_t smb = (uint32_t)__cvta_generic_to_shared(smraw);
    const uint32_t smW = smb;
    const uint32_t smS = smb + (uint32_t)(ECH*32*72*2);
    const int t = threadIdx.x;
    const int lane = t & 31, w = t >> 5;
    const int wm = w & 3, wn = w >> 2;
    const int nbase = blockIdx.x*32;
    const int g2 = lane >> 2, q2 = (lane & 3)*2;
    const int b = t & 127;
    const int jj0 = (t >> 7)*4;
    const int jbase = (nbase >> 2) + jj0;
    const int Lb = lens[b];
    __half z16 = __float2half(0.f);

    float creg[4] = {0.f, 0.f, 0.f, 0.f};
    __half hreg[4] = {z16, z16, z16, z16};
    float bgate[4][4];
#pragma unroll
    for (int idx = 0; idx < 4; idx++) {
        int jglob = jbase + idx;
        bgate[idx][0] = biasv[jglob];
        bgate[idx][1] = biasv[1024 + jglob];
        bgate[idx][2] = biasv[2048 + jglob];
        bgate[idx][3] = biasv[3072 + jglob];
    }

    load_resident<ECH>(smW, t, g_WerH, KE, nbase);

    unsigned target = 0;
    for (int s = 0; s < S_SRC; s++) {
        const int p = s & 1;
        const __half* Ah = g_eh + p*B*H;
        __half* Ho = g_eh + (p^1)*B*H;
        const float* add = g_encpre + (int64_t)s*B*4096;

        float acc[2][2][4];
#pragma unroll
        for (int a = 0; a < 2; a++)
#pragma unroll
            for (int b2 = 0; b2 < 2; b2++)
#pragma unroll
                for (int r = 0; r < 4; r++) acc[a][b2][r] = 0.f;

        gemm_phase<ECH>(smW, smS, t, lane, wm, wn, Ah, H, g_WerL, KE, nbase, acc);

        float* zb = (float*)(smraw + ECH*32*72*2);
#pragma unroll
        for (int mf = 0; mf < 2; mf++)
#pragma unroll
            for (int nf = 0; nf < 2; nf++)
#pragma unroll
                for (int r = 0; r < 4; r++) {
                    int row = wm*32 + mf*16 + g2 + (r >> 1)*8;
                    int col = wn*16 + nf*8 + q2 + (r & 1);
                    zb[row*33 + col] = acc[mf][nf][r];
                }
        __syncthreads();

        const bool valid = s < Lb;
        __half shout[4];
#pragma unroll
        for (int idx = 0; idx < 4; idx++) {
            int jj = jj0 + idx;
            float4 pre = *(const float4*)&add[(int64_t)b*4096 + nbase + jj*4];
            float zi = zb[b*33 + jj*4 + 0] + pre.x + bgate[idx][0];
            float zf = zb[b*33 + jj*4 + 1] + pre.y + bgate[idx][1];
            float zg = zb[b*33 + jj*4 + 2] + pre.z + bgate[idx][2];
            float zo = zb[b*33 + jj*4 + 3] + pre.w + bgate[idx][3];
            float c2 = sig_ap(zf)*creg[idx] + sig_ap(zi)*tanh_ap(zg);
            float h2 = sig_ap(zo)*tanh_ap(c2);
            if (valid) { creg[idx] = c2; hreg[idx] = __float2half(h2); }
            shout[idx] = valid ? hreg[idx] : z16;
        }
        *(uint2*)&Ho[b*H + jbase] = *(uint2*)hreg;
        *(uint2*)&g_sh[((int64_t)b*S_SRC + s)*H + jbase] = *(uint2*)shout;
        grid_sync(&g_bar1, target += 128);
    }
#pragma unroll
    for (int idx = 0; idx < 4; idx++)
        g_ec[b*H + jbase + idx] = creg[idx];
}

// ---------------- persistent decoder ----------------
__device__ __forceinline__ void stream_mini(uint32_t st, int t, int k0,
    const __half* __restrict__ A, int nb8)
{
#pragma unroll
    for (int i = 0; i < 5; i++) {
        int u = i*256 + t;
        if (u >= 1152) break;
        int row = u >> 3, grp = u & 7;
        const __half* src;
        if (row < 128)      src = A + (int64_t)row*KDR + k0 + grp*8;
        else if (row < 136) src = g_WaH + (int64_t)(nb8 + row - 128)*1024 + k0 + grp*8;
        else                src = g_WaL + (int64_t)(nb8 + row - 136)*1024 + k0 + grp*8;
        cpa16(st + (uint32_t)(row*72 + grp*8)*2u, src);
    }
    CP_COMMIT;
}

__global__ __launch_bounds__(256) void dec_persist(const float* __restrict__ biasv,
                                                   const float* __restrict__ ba_,
                                                   const int* __restrict__ lens,
                                                   float* __restrict__ outF) {
    extern __shared__ char smraw[];
    __shared__ float s_ak[112];
    __shared__ float s_en[128];
    __shared__ float s_red[8];
    const uint32_t smb = (uint32_t)__cvta_generic_to_shared(smraw);
    const uint32_t smW = smb;
    const uint32_t smS = smb + (uint32_t)(DCH*32*72*2);
    const int t = threadIdx.x;
    const int lane = t & 31, w = t >> 5;
    const int wm = w & 3, wn = w >> 2;
    const int nbase = blockIdx.x*32;
    const int g2 = lane >> 2, q2 = (lane & 3)*2;
    const int myb = blockIdx.x;
    const int b = t & 127;
    const int jj0 = (t >> 7)*4;
    const int jbase = (nbase >> 2) + jj0;

    float creg[4];
    float bgate[4][4];
#pragma unroll
    for (int idx = 0; idx < 4; idx++) {
        int jglob = jbase + idx;
        creg[idx] = g_dc[b*H + jglob];
        bgate[idx][0] = biasv[jglob];
        bgate[idx][1] = biasv[1024 + jglob];
        bgate[idx][2] = biasv[2048 + jglob];
        bgate[idx][3] = biasv[3072 + jglob];
    }

    load_resident<DCH>(smW, t, g_WdrH, KDR, nbase);

    unsigned target = 0;
    for (int ts = 0; ts < S_TRG; ts++) {
        const int p = ts & 1;
        __half* dAp = g_dA + p*B*KDR;
        __half* nAp = g_dA + (p^1)*B*KDR;

        // A1: a_key mini-GEMM (blocks 0..13, N=8, W hi/lo 2-pass)
        if (blockIdx.x < 14) {
            const int nb8 = blockIdx.x*8;
            float acm[4] = {0.f,0.f,0.f,0.f};
            stream_mini(smS, t, 0, dAp, nb8);
            for (int c = 0; c < 16; c++) {
                if (c < 15) stream_mini(smS + ((c+1)&1)*STGB, t, (c+1)*64, dAp, nb8);
                if (c < 15) { CP_WAIT1; } else { CP_WAIT0; }
                __syncthreads();
                uint32_t st = smS + (c & 1)*STGB;
#pragma unroll
                for (int kk16 = 0; kk16 < 64; kk16 += 16) {
                    uint32_t bh[2], bl[2];
                    int rowW = lane & 7;
                    int kcolW = kk16 + ((lane >> 3) & 1)*8;
                    ldmx2(st + (uint32_t)((128 + rowW)*72 + kcolW)*2u, bh);
                    ldmx2(st + (uint32_t)((136 + rowW)*72 + kcolW)*2u, bl);
                    int rowA = w*16 + (lane & 7) + ((lane >> 3) & 1)*8;
                    int kcolA = kk16 + ((lane >> 4) & 1)*8;
                    uint32_t a4[4];
                    ldmx4(st + (uint32_t)(rowA*72 + kcolA)*2u, a4);
                    mma16816(acm, a4, bh);
                    mma16816(acm, a4, bl);
                }
                __syncthreads();
            }
#pragma unroll
            for (int r = 0; r < 4; r++) {
                int row = w*16 + g2 + (r >> 1)*8;
                int gc = nb8 + q2 + (r & 1);
                float bb = (gc < 100) ? ba_[gc] : 0.f;
                g_akey[row*112 + gc] = tanh_ap(acm[r] + bb);
            }
        }
        grid_sync(&g_bar2, target += 128);

        // A2: softmax + context for batch myb (qkey reads vectorized)
        {
            if (t < 112) s_ak[t] = g_akey[myb*112 + t];
            __syncthreads();
            float ex = 0.f;
            if (t < 128) {
                int L = lens[myb];
                const float4* qk = (const float4*)(g_qkey + ((int64_t)myb*S_SRC + t)*112);
                float pp = 0.f;
#pragma unroll
                for (int d4 = 0; d4 < 25; d4++) {
                    float4 qv = qk[d4];
                    pp = fmaf(qv.x, s_ak[d4*4+0], pp);
                    pp = fmaf(qv.y, s_ak[d4*4+1], pp);
                    pp = fmaf(qv.z, s_ak[d4*4+2], pp);
                    pp = fmaf(qv.w, s_ak[d4*4+3], pp);
                }
                float e = (t < L) ? pp : -1e9f;
                float mx = e;
                for (int o = 16; o; o >>= 1) mx = fmaxf(mx, __shfl_xor_sync(0xffffffffu, mx, o));
                if (lane == 0) s_red[w] = mx;
                s_en[t] = e;
            }
            __syncthreads();
            if (t < 128) {
                float mx = fmaxf(fmaxf(s_red[0], s_red[1]), fmaxf(s_red[2], s_red[3]));
                ex = expf(s_en[t] - mx);
                float sm = ex;
                for (int o = 16; o; o >>= 1) sm += __shfl_xor_sync(0xffffffffu, sm, o);
                if (lane == 0) s_red[4 + w] = sm;
            }
            __syncthreads();
            if (t < 128) s_en[t] = ex;
            __syncthreads();
            float denom = s_red[4] + s_red[5] + s_red[6] + s_red[7];
            for (int d = t; d < 300; d += 256) {
                float c = 0.f;
#pragma unroll 4
                for (int s2 = 0; s2 < S_SRC; s2++)
                    c = fmaf(s_en[s2], g_qval[((int64_t)myb*S_SRC + s2)*304 + d], c);
                c /= denom;
                dAp[(int64_t)myb*KDR + 1024 + d] = __float2half(c);
            }
        }
        grid_sync(&g_bar2, target += 128);

        // B: recurrent GEMM + LSTM epilogue (vectorized stores)
        {
            const float* add = g_decpre + (int64_t)ts*B*4096;
            float acc[2][2][4];
#pragma unroll
            for (int a = 0; a < 2; a++)
#pragma unroll
                for (int b2 = 0; b2 < 2; b2++)
#pragma unroll
                    for (int r = 0; r < 4; r++) acc[a][b2][r] = 0.f;

            gemm_phase<DCH>(smW, smS, t, lane, wm, wn, dAp, KDR, g_WdrL, KDR, nbase, acc);

            float* zb = (float*)(smraw + DCH*32*72*2);
#pragma unroll
            for (int mf = 0; mf < 2; mf++)
#pragma unroll
                for (int nf = 0; nf < 2; nf++)
#pragma unroll
                    for (int r = 0; r < 4; r++) {
                        int row = wm*32 + mf*16 + g2 + (r >> 1)*8;
                        int col = wn*16 + nf*8 + q2 + (r & 1);
                        zb[row*33 + col] = acc[mf][nf][r];
                    }
            __syncthreads();

            __half hpack[4];
            float4 opack;
            float* op = (float*)&opack;
#pragma unroll
            for (int idx = 0; idx < 4; idx++) {
                int jj = jj0 + idx;
                float4 pre = *(const float4*)&add[(int64_t)b*4096 + nbase + jj*4];
                float zi = zb[b*33 + jj*4 + 0] + pre.x + bgate[idx][0];
                float zf = zb[b*33 + jj*4 + 1] + pre.y + bgate[idx][1];
                float zg = zb[b*33 + jj*4 + 2] + pre.z + bgate[idx][2];
                float zo = zb[b*33 + jj*4 + 3] + pre.w + bgate[idx][3];
                float c2 = sig_ap(zf)*creg[idx] + sig_ap(zi)*tanh_ap(zg);
                float h2 = sig_ap(zo)*tanh_ap(c2);
                creg[idx] = c2;
                hpack[idx] = __float2half(h2);
                op[idx] = h2;
            }
            *(uint2*)&nAp[(int64_t)b*KDR + jbase] = *(uint2*)hpack;
            *(float4*)&outF[((int64_t)b*S_TRG + ts)*H + jbase] = opack;
        }
        grid_sync(&g_bar2, target += 128);
    }
}

// ---------------- one-shot GEMM (R14, pipelined ldmatrix) ----------------
__device__ __forceinline__ void load_chunk_g(uint32_t smb, int buf, int t, int k0,
    const __half* __restrict__ A, int ldA, int mbase,
    const __half* __restrict__ Wh, const __half* __restrict__ Wl, int ldW, int nbase)
{
#pragma unroll
    for (int i = 0; i < 4; i++) {
        int u = i*256 + t;
        int row = u >> 3, grp = u & 7;
        const __half* src = A + (int64_t)(mbase + row)*ldA + k0 + grp*8;
        cpa16(smb + (uint32_t)buf*18432u + (uint32_t)(row*72 + grp*8)*2u, src);
    }
#pragma unroll
    for (int i = 0; i < 2; i++) {
        int u = i*256 + t;
        int hl = u >> 8, rem = u & 255;
        int row = rem >> 3, grp = rem & 7;
        const __half* src = (hl ? Wl : Wh) + (int64_t)(nbase + row)*ldW + k0 + grp*8;
        cpa16(smb + 36864u + (uint32_t)(((buf*2 + hl)*32 + row)*72 + grp*8)*2u, src);
    }
    CP_COMMIT;
}

__device__ __forceinline__ void ldB2g(uint32_t wbh, uint32_t wbl, int lane, int wn, int kk16,
                                      uint32_t bh[2][2], uint32_t bl[2][2]) {
#pragma unroll
    for (int nf = 0; nf < 2; nf++) {
        int rowW = wn*16 + nf*8 + (lane & 7);
        int kcol = kk16 + ((lane >> 3) & 1)*8;
        ldmx2(wbh + (uint32_t)(rowW*72 + kcol)*2u, bh[nf]);
        ldmx2(wbl + (uint32_t)(rowW*72 + kcol)*2u, bl[nf]);
    }
}
__device__ __forceinline__ void ldA2g(uint32_t ab, int lane, int wm, int kk16, uint32_t a4[2][4]) {
#pragma unroll
    for (int mf = 0; mf < 2; mf++) {
        int rowA = wm*32 + mf*16 + (lane & 7) + ((lane >> 3) & 1)*8;
        int kcol = kk16 + ((lane >> 4) & 1)*8;
        ldmx4(ab + (uint32_t)(rowA*72 + kcol)*2u, a4[mf]);
    }
}

template<int OUT, int ACT>
__global__ __launch_bounds__(256) void mma_gemm(
    const __half* __restrict__ A, int ldA,
    const __half* __restrict__ Wh, const __half* __restrict__ Wl, int ldW,
    int N, int KT, const float* __restrict__ bias,
    float* __restrict__ Cf, __half* __restrict__ Ch, int ldC)
{
    extern __shared__ char smraw[];
    uint32_t smb = (uint32_t)__cvta_generic_to_shared(smraw);
    const int t = threadIdx.x;
    const int lane = t & 31, w = t >> 5;
    const int wm = w & 3, wn = w >> 2;
    const int mbase = blockIdx.y*128;
    const int nbase = blockIdx.x*32;

    float acc[2][2][4];
#pragma unroll
    for (int a = 0; a < 2; a++)
#pragma unroll
        for (int b2 = 0; b2 < 2; b2++)
#pragma unroll
            for (int r = 0; r < 4; r++) acc[a][b2][r] = 0.f;

    load_chunk_g(smb, 0, t, 0, A, ldA, mbase, Wh, Wl, ldW, nbase);

    for (int kc = 0; kc < KT; kc++) {
        const int cur = kc & 1;
        if (kc + 1 < KT) {
            load_chunk_g(smb, cur ^ 1, t, (kc+1)*64, A, ldA, mbase, Wh, Wl, ldW, nbase);
            CP_WAIT1;
        } else { CP_WAIT0; }
        __syncthreads();

        const uint32_t ab  = smb + (uint32_t)cur*18432u;
        const uint32_t wbh = smb + 36864u + (uint32_t)((cur*2+0)*32*72)*2u;
        const uint32_t wbl = smb + 36864u + (uint32_t)((cur*2+1)*32*72)*2u;
        uint32_t bh[2][2][2], bl[2][2][2], a4[2][2][4];
        ldB2g(wbh, wbl, lane, wn, 0, bh[0], bl[0]);
        ldA2g(ab, lane, wm, 0, a4[0]);
#pragma unroll
        for (int k = 0; k < 4; k++) {
            const int c2 = k & 1, nx = c2 ^ 1;
            if (k < 3) {
                ldB2g(wbh, wbl, lane, wn, (k+1)*16, bh[nx], bl[nx]);
                ldA2g(ab, lane, wm, (k+1)*16, a4[nx]);
            }
#pragma unroll
            for (int mf = 0; mf < 2; mf++)
#pragma unroll
                for (int nf = 0; nf < 2; nf++) {
                    mma16816(acc[mf][nf], a4[c2][mf], bh[c2][nf]);
                    mma16816(acc[mf][nf], a4[c2][mf], bl[c2][nf]);
                }
        }
        __syncthreads();
    }

    const int g2 = lane >> 2, q2 = (lane & 3)*2;
#pragma unroll
    for (int mf = 0; mf < 2; mf++)
#pragma unroll
        for (int nf = 0; nf < 2; nf++)
#pragma unroll
            for (int r = 0; r < 4; r++) {
                int row = mbase + wm*32 + mf*16 + g2 + (r >> 1)*8;
                int col = nbase + wn*16 + nf*8 + q2 + (r & 1);
                if (col < N) {
                    float v = acc[mf][nf][r];
                    if (bias) v += bias[col];
                    if (ACT == 1) v = fmaxf(v, 0.f);
                    if (ACT == 2) v = tanhf(v);
                    if (OUT == 0) Cf[(int64_t)row*ldC + col] = v;
                    else Ch[(int64_t)row*ldC + col] = __float2half(v);
                }
            }
}

// ---------------- launcher ----------------
#define GSA(p, s) cudaGetSymbolAddress((void**)&p, s)

extern "C" void kernel_launch(void* const* d_in, const int* in_sizes, int n_in,
                              void* d_out, int out_size) {
    const int* src_seqs = (const int*)d_in[0];
    const int* src_len = (const int*)d_in[1];
    const int* trg_nt = (const int*)d_in[2];
    const int* par_nt = (const int*)d_in[3];
    const int* par_lex = (const int*)d_in[4];
    const float* lex_emb = (const float*)d_in[5];
    const float* nt_emb = (const float*)d_in[6];
    const float* enc_Wih = (const float*)d_in[7];
    const float* enc_Whh = (const float*)d_in[8];
    const float* enc_b = (const float*)d_in[9];
    const float* dec_Wih = (const float*)d_in[10];
    const float* dec_Whh = (const float*)d_in[11];
    const float* dec_b = (const float*)d_in[12];
    const float* Wh1 = (const float*)d_in[13];
    const float* bh1 = (const float*)d_in[14];
    const float* Wh2 = (const float*)d_in[15];
    const float* bh2 = (const float*)d_in[16];
    const float* Wc1 = (const float*)d_in[17];
    const float* bc1 = (const float*)d_in[18];
    const float* Wc2 = (const float*)d_in[19];
    const float* bc2 = (const float*)d_in[20];
    const float* Wa = (const float*)d_in[21];
    const float* ba = (const float*)d_in[22];
    const float* Wqk = (const float*)d_in[23];
    const float* bqk = (const float*)d_in[24];
    const float* Wqv = (const float*)d_in[25];
    const float* bqv = (const float*)d_in[26];
    float* out = (float*)d_out;

    cudaFuncSetAttribute(mma_gemm<0,0>, cudaFuncAttributeMaxDynamicSharedMemorySize, GEN_SMEM);
    cudaFuncSetAttribute(mma_gemm<0,2>, cudaFuncAttributeMaxDynamicSharedMemorySize, GEN_SMEM);
    cudaFuncSetAttribute(mma_gemm<1,0>, cudaFuncAttributeMaxDynamicSharedMemorySize, GEN_SMEM);
    cudaFuncSetAttribute(mma_gemm<1,1>, cudaFuncAttributeMaxDynamicSharedMemorySize, GEN_SMEM);
    cudaFuncSetAttribute(enc_persist, cudaFuncAttributeMaxDynamicSharedMemorySize, ENC_SMEM);
    cudaFuncSetAttribute(dec_persist, cudaFuncAttributeMaxDynamicSharedMemorySize, DEC_SMEM);

    __half *WerH,*WerL,*WdrH,*WdrL,*WaH,*WaL;
    __half *WeiH,*WeiL,*WdiH,*WdiL,*WqkH,*WqkL,*WqvH,*WqvL;
    __half *Wh1H,*Wh1L,*Wh2H,*Wh2L,*Wc1H,*Wc1L,*Wc2H,*Wc2L;
    __half *se,*ae,*sh,*eh,*dA,*ecA,*t1;
    float *encpre,*decpre,*qkey,*qval,*ec,*dc;
    GSA(WerH,g_WerH); GSA(WerL,g_WerL); GSA(WdrH,g_WdrH); GSA(WdrL,g_WdrL);
    GSA(WaH,g_WaH);   GSA(WaL,g_WaL);
    GSA(WeiH,g_WeiH); GSA(WeiL,g_WeiL); GSA(WdiH,g_WdiH); GSA(WdiL,g_WdiL);
    GSA(WqkH,g_WqkH); GSA(WqkL,g_WqkL); GSA(WqvH,g_WqvH); GSA(WqvL,g_WqvL);
    GSA(Wh1H,g_Wh1H); GSA(Wh1L,g_Wh1L); GSA(Wh2H,g_Wh2H); GSA(Wh2L,g_Wh2L);
    GSA(Wc1H,g_Wc1H); GSA(Wc1L,g_Wc1L); GSA(Wc2H,g_Wc2H); GSA(Wc2L,g_Wc2L);
    GSA(se,g_se); GSA(ae,g_ae); GSA(sh,g_sh); GSA(eh,g_eh); GSA(dA,g_dA);
    GSA(ecA,g_ecA); GSA(t1,g_t1);
    GSA(encpre,g_encpre); GSA(decpre,g_decpre);
    GSA(qkey,g_qkey); GSA(qval,g_qval); GSA(ec,g_ec); GSA(dc,g_dc);

    convw_enc_kernel<<<1024, 256>>>(enc_Whh, enc_Wih);
    gather_kernel<<<2048, 256>>>(src_seqs, trg_nt, par_nt, par_lex, lex_emb, nt_emb);
    mma_gemm<0,0><<<dim3(128,128), 256, GEN_SMEM>>>(se, KSE, WeiH, WeiL, KSE,
        4096, KSE/64, nullptr, encpre, nullptr, 4096);

    // L3: encoder persistent (ncu capture target)
    enc_persist<<<128, 256, ENC_SMEM>>>(enc_b, src_len);

    convw_kernel<<<1024, 256>>>(WdrH, WdrL, dec_Whh, dec_Wih, 4096, 0, KDR, 1324, 0, 2);
    convw_kernel<<<1024, 256>>>(WdiH, WdiL, dec_Wih, nullptr, 4096, 0, KAE, 556, 856, 1);
    convw_kernel<<<256, 256>>>(WqkH, WqkL, Wqk, nullptr, 128, 100, 1024, 1024, 1024, 0);
    convw_kernel<<<256, 256>>>(WqvH, WqvL, Wqv, nullptr, 320, 300, 1024, 1024, 1024, 0);
    convw_kernel<<<256, 256>>>(WaH,  WaL,  Wa,  nullptr, 128, 100, 1024, 1024, 1024, 0);
    convw_kernel<<<1024, 256>>>(Wh1H, Wh1L, Wh1, nullptr, 2048, 2048, 1024, 1024, 1024, 0);
    convw_kernel<<<1024, 256>>>(Wh2H, Wh2L, Wh2, nullptr, 1024, 1024, 2048, 2048, 2048, 0);
    convw_kernel<<<1024, 256>>>(Wc1H, Wc1L, Wc1, nullptr, 2048, 2048, 1024, 1024, 1024, 0);
    convw_kernel<<<1024, 256>>>(Wc2H, Wc2L, Wc2, nullptr, 1024, 1024, 2048, 2048, 2048, 0);

    mma_gemm<0,0><<<dim3(128,64), 256, GEN_SMEM>>>(ae, KAE, WdiH, WdiL, KAE,
        4096, KAE/64, nullptr, decpre, nullptr, 4096);

    mma_gemm<0,2><<<dim3(4,128), 256, GEN_SMEM>>>(sh, H, WqkH, WqkL, 1024,
        100, 16, bqk, qkey, nullptr, 112);
    mma_gemm<0,0><<<dim3(10,128), 256, GEN_SMEM>>>(sh, H, WqvH, WqvL, 1024,
        300, 16, bqv, qval, nullptr, 304);

    convw_kernel<<<256, 256>>>(ecA, nullptr, ec, nullptr, 128, 128, 1024, 1024, 1024, 0);
    mma_gemm<1,1><<<dim3(64,1), 256, GEN_SMEM>>>(eh, H, Wh1H, Wh1L, 1024,
        2048, 16, bh1, nullptr, t1, 2048);
    mma_gemm<1,0><<<dim3(32,1), 256, GEN_SMEM>>>(t1, 2048, Wh2H, Wh2L, 2048,
        1024, 32, bh2, nullptr, dA, KDR);
    mma_gemm<1,1><<<dim3(64,1), 256, GEN_SMEM>>>(ecA, H, Wc1H, Wc1L, 1024,
        2048, 16, bc1, nullptr, t1, 2048);
    mma_gemm<0,0><<<dim3(32,1), 256, GEN_SMEM>>>(t1, 2048, Wc2H, Wc2L, 2048,
        1024, 32, bc2, dc, nullptr, 1024);

    dec_persist<<<128, 256, DEC_SMEM>>>(dec_b, ba, src_len, out);
}